// round 5
// baseline (speedup 1.0000x reference)
#include <cuda_runtime.h>

#define BATCH 4
#define NPTS 4096
#define KOUT 16
#define NEED 31                 // rank 0 plus ranks 16..30
#define R2 256.0f
#define NTILES (NPTS / 32)      // 128
#define TPB 256
#define WARPS (TPB / 32)        // 8
#define NBLOCKS 296             // 148 SMs * 2 resident blocks
#define WPB_PER_BATCH ((NBLOCKS / BATCH) * WARPS)        // 592
#define PERIOD (NPTS + WPB_PER_BATCH)                    // 4688
#define NK ((size_t)NPTS * KOUT)                         // 65536
#define SPAD 128                // prefetch overrun pad (float4)

// steal counters: never reset; q = ctr % PERIOD is deterministic per replay
__device__ unsigned g_ctr[BATCH];

// exact arithmetic (matches reference decisions; rel_err 0.0 with this)
__device__ __forceinline__ float dist2(float4 a, float4 b) {
    float dot = __fadd_rn(
        __fadd_rn(__fmul_rn(a.x, b.x), __fmul_rn(a.y, b.y)),
        __fmul_rn(a.z, b.z));
    return __fsub_rn(__fadd_rn(a.w, b.w), __fmul_rn(2.0f, dot));
}

// ---------------------------------------------------------------------------
// Fused kernel: ball query + dilated selection + transposing gather epilogue.
// ---------------------------------------------------------------------------
__global__ void __launch_bounds__(TPB, 2) fused_kernel(
        const float* __restrict__ xyz,
        const float* __restrict__ feat,
        float* __restrict__ out) {
    extern __shared__ float4 s[];                // (4096 + SPAD) float4
    __shared__ __align__(16) unsigned words[WARPS][NTILES];
    __shared__ int oid[WARPS][KOUT + 1];
    __shared__ float4 stage[WARPS][256];         // 16 rows x 16 float4 / warp

    int b = blockIdx.x % BATCH;
    const float* xb = xyz + (size_t)b * NPTS * 3;

    for (int i = threadIdx.x; i < NPTS; i += blockDim.x) {
        float x = xb[3 * i + 0];
        float y = xb[3 * i + 1];
        float z = xb[3 * i + 2];
        float nq = __fadd_rn(__fadd_rn(__fmul_rn(x, x), __fmul_rn(y, y)),
                             __fmul_rn(z, z));
        s[i] = make_float4(x, y, z, nq);
    }
    // zero the prefetch pad (values never used in decisions, but keep defined)
    for (int i = threadIdx.x; i < SPAD; i += blockDim.x)
        s[NPTS + i] = make_float4(0.f, 0.f, 0.f, 0.f);
    __syncthreads();

    int warp = threadIdx.x >> 5;
    int lane = threadIdx.x & 31;
    const float* fb = feat + (size_t)b * NPTS * 64;
    float* outx = out + ((size_t)b * 3) * NK;                 // xyz block
    float* outf = out + (size_t)BATCH * 3 * NK + ((size_t)b * 64) * NK;

    for (;;) {
        unsigned qr = 0;
        if (lane == 0) qr = atomicAdd(&g_ctr[b], 1u) % PERIOD;
        int q = __shfl_sync(0xffffffffu, (int)qr, 0);
        if (q >= NPTS) break;

        float4 pn = s[q];
        int cnt = 0;
        int tscan;

        // ---- scan: 4 tiles / iter, next-iter loads prefetched ----
        {
            const float4* sp = s + lane;
            float4 p0 = sp[0], p1 = sp[32], p2 = sp[64], p3 = sp[96];
            int c = 0;
            for (;;) {
                sp += 128;
                float4 n0 = sp[0], n1 = sp[32], n2 = sp[64], n3 = sp[96];
                float d0 = dist2(pn, p0);
                float d1 = dist2(pn, p1);
                float d2 = dist2(pn, p2);
                float d3 = dist2(pn, p3);
                unsigned m0 = __ballot_sync(0xffffffffu, d0 < R2);
                unsigned m1 = __ballot_sync(0xffffffffu, d1 < R2);
                unsigned m2 = __ballot_sync(0xffffffffu, d2 < R2);
                unsigned m3 = __ballot_sync(0xffffffffu, d3 < R2);
                if (lane == 0)
                    *(uint4*)&words[warp][c] = make_uint4(m0, m1, m2, m3);
                cnt += __popc(m0) + __popc(m1) + __popc(m2) + __popc(m3);
                c += 4;
                if (cnt >= NEED || c >= NTILES) { tscan = c; break; }
                p0 = n0; p1 = n1; p2 = n2; p3 = n3;
            }
        }
        __syncwarp();

        // ---- decode: rank 0 and ranks 16..30 from mask words ----
        int base = 0;
#pragma unroll
        for (int g = 0; g < 4; g++) {
            if (base >= NEED) break;
            int wi = 32 * g + lane;
            unsigned w = (wi < tscan) ? words[warp][wi] : 0u;
            int pc = __popc(w);
            int pre = pc;                          // inclusive warp scan
#pragma unroll
            for (int o = 1; o < 32; o <<= 1) {
                int t = __shfl_up_sync(0xffffffffu, pre, o);
                if (lane >= o) pre += t;
            }
            int lo = base + pre - pc;              // first rank in my word
            if (w && lo < NEED) {
                unsigned ww = w;
                int r = lo;
                while (ww && r < NEED) {
                    int bit = __ffs(ww) - 1;
                    ww &= ww - 1;
                    if (r == 0)
                        oid[warp][0] = 32 * wi + bit;
                    else if (r >= 16)
                        oid[warp][r - 15] = 32 * wi + bit;
                    r++;
                }
            }
            base += __shfl_sync(0xffffffffu, pre, 31);
        }
        __syncwarp();

        // finalize ids (padding with first hit) back into oid[warp][k]
        if (lane < KOUT) {
            int v = (lane > 0 && cnt >= lane + 16) ? oid[warp][lane]
                                                   : oid[warp][0];
            oid[warp][lane] = v;
        }
        __syncwarp();

        // ---- gather epilogue ----
        // xyz: straight from smem (lanes 0..15, k = lane)
        if (lane < KOUT) {
            float4 p = s[oid[warp][lane]];
            size_t ox = (size_t)q * KOUT + lane;
            outx[ox]          = p.x;
            outx[ox + NK]     = p.y;
            outx[ox + 2 * NK] = p.z;
        }

        // feat load: coalesced rows -> XOR-swizzled smem stage.
        // instr i loads rows 2i (lanes 0-15) and 2i+1 (lanes 16-31); each lane
        // grabs one 16B chunk of its row -> 4 wavefronts per LDG.128.
        {
            int rsel  = lane >> 4;       // which of the 2 rows
            int chunk = lane & 15;       // 16B chunk within row
#pragma unroll
            for (int i = 0; i < 8; i++) {
                int row = 2 * i + rsel;
                int id = oid[warp][row];
                float4 v = *((const float4*)(fb + (size_t)id * 64) + chunk);
                stage[warp][row * 16 + (chunk ^ row)] = v;
            }
        }
        __syncwarp();

        // feat store: lane l -> (k = l&15, half = l>>4); channel-major STGs
        // land as 2 x 64B segments per instruction.
        {
            int k    = lane & 15;
            int half = lane >> 4;
            float* ob = outf + (size_t)(half * 32) * NK + (size_t)q * KOUT + k;
#pragma unroll
            for (int t = 0; t < 8; t++) {
                float4 v = stage[warp][k * 16 + ((half * 8 + t) ^ k)];
                float* o = ob + (size_t)(t * 4) * NK;
                o[0]      = v.x;
                o[NK]     = v.y;
                o[2 * NK] = v.z;
                o[3 * NK] = v.w;
            }
        }
        __syncwarp();
    }
}

extern "C" void kernel_launch(void* const* d_in, const int* in_sizes, int n_in,
                              void* d_out, int out_size) {
    const float* xyz  = (const float*)d_in[0];
    const float* feat = (const float*)d_in[1];
    float* out = (float*)d_out;

    cudaFuncSetAttribute(fused_kernel,
                         cudaFuncAttributeMaxDynamicSharedMemorySize,
                         (NPTS + SPAD) * sizeof(float4));

    fused_kernel<<<NBLOCKS, TPB, (NPTS + SPAD) * sizeof(float4)>>>(
        xyz, feat, out);
}

// round 7
// speedup vs baseline: 1.1356x; 1.1356x over previous
#include <cuda_runtime.h>

#define BATCH 4
#define NPTS 4096
#define KOUT 16
#define NEED 31                 // rank 0 plus ranks 16..30
#define R2 256.0f
#define NTILES (NPTS / 32)      // 128
#define TPB 512
#define WARPS (TPB / 32)        // 16
#define NBLOCKS 296             // 148 SMs * 2 resident blocks
#define WPB_PER_BATCH ((NBLOCKS / BATCH) * WARPS)        // 1184
#define PERIOD (NPTS + WPB_PER_BATCH)                    // 5280
#define NK ((size_t)NPTS * KOUT)                         // 65536

// steal counters: never reset; q = ctr % PERIOD is deterministic per replay
__device__ unsigned g_ctr[BATCH];

// exact arithmetic (matches reference decisions; rel_err 0.0 with this)
__device__ __forceinline__ float dist2(float4 a, float4 b) {
    float dot = __fadd_rn(
        __fadd_rn(__fmul_rn(a.x, b.x), __fmul_rn(a.y, b.y)),
        __fmul_rn(a.z, b.z));
    return __fsub_rn(__fadd_rn(a.w, b.w), __fmul_rn(2.0f, dot));
}

// ---------------------------------------------------------------------------
// Fused kernel: ball query + dilated selection + transposing gather epilogue.
// Warp per query (work-stealing), 2-pass channel-half transpose in smem.
// ---------------------------------------------------------------------------
__global__ void __launch_bounds__(TPB, 2) fused_kernel(
        const float* __restrict__ xyz,
        const float* __restrict__ feat,
        float* __restrict__ out) {
    extern __shared__ float4 s[];                       // 4096 float4 = 64KB
    __shared__ __align__(16) unsigned words[WARPS][NTILES];
    __shared__ int oid[WARPS][KOUT + 1];
    __shared__ float4 stage[WARPS][128];                // 16 rows x 8 f4 = 2KB

    int b = blockIdx.x % BATCH;
    const float* xb = xyz + (size_t)b * NPTS * 3;

    for (int i = threadIdx.x; i < NPTS; i += blockDim.x) {
        float x = xb[3 * i + 0];
        float y = xb[3 * i + 1];
        float z = xb[3 * i + 2];
        float nq = __fadd_rn(__fadd_rn(__fmul_rn(x, x), __fmul_rn(y, y)),
                             __fmul_rn(z, z));
        s[i] = make_float4(x, y, z, nq);
    }
    __syncthreads();

    int warp = threadIdx.x >> 5;
    int lane = threadIdx.x & 31;
    const float* fb = feat + (size_t)b * NPTS * 64;
    float* outx = out + ((size_t)b * 3) * NK;                 // xyz block
    float* outf = out + (size_t)BATCH * 3 * NK + ((size_t)b * 64) * NK;

    for (;;) {
        unsigned qr = 0;
        if (lane == 0) qr = atomicAdd(&g_ctr[b], 1u) % PERIOD;
        int q = __shfl_sync(0xffffffffu, (int)qr, 0);
        if (q >= NPTS) break;

        float4 pn = s[q];
        int cnt = 0;
        int tscan = NTILES;

        // ---- scan: 4 tiles (128 candidates) per iteration ----
        {
            const float4* sp = s + lane;
            for (int c = 0; c < NTILES; c += 4, sp += 128) {
                float4 p0 = sp[0];
                float4 p1 = sp[32];
                float4 p2 = sp[64];
                float4 p3 = sp[96];
                float d0 = dist2(pn, p0);
                float d1 = dist2(pn, p1);
                float d2 = dist2(pn, p2);
                float d3 = dist2(pn, p3);
                unsigned m0 = __ballot_sync(0xffffffffu, d0 < R2);
                unsigned m1 = __ballot_sync(0xffffffffu, d1 < R2);
                unsigned m2 = __ballot_sync(0xffffffffu, d2 < R2);
                unsigned m3 = __ballot_sync(0xffffffffu, d3 < R2);
                if (lane == 0)
                    *(uint4*)&words[warp][c] = make_uint4(m0, m1, m2, m3);
                cnt += __popc(m0) + __popc(m1) + __popc(m2) + __popc(m3);
                if (cnt >= NEED) { tscan = c + 4; break; }
            }
        }
        __syncwarp();

        // ---- decode: rank 0 and ranks 16..30 from mask words ----
        int base = 0;
#pragma unroll
        for (int g = 0; g < 4; g++) {
            if (base >= NEED) break;
            int wi = 32 * g + lane;
            unsigned w = (wi < tscan) ? words[warp][wi] : 0u;
            int pc = __popc(w);
            int pre = pc;                          // inclusive warp scan
#pragma unroll
            for (int o = 1; o < 32; o <<= 1) {
                int t = __shfl_up_sync(0xffffffffu, pre, o);
                if (lane >= o) pre += t;
            }
            int lo = base + pre - pc;              // first rank in my word
            if (w && lo < NEED) {
                unsigned ww = w;
                int r = lo;
                while (ww && r < NEED) {
                    int bit = __ffs(ww) - 1;
                    ww &= ww - 1;
                    if (r == 0)
                        oid[warp][0] = 32 * wi + bit;
                    else if (r >= 16)
                        oid[warp][r - 15] = 32 * wi + bit;
                    r++;
                }
            }
            base += __shfl_sync(0xffffffffu, pre, 31);
        }
        __syncwarp();

        // finalize ids (padding with first hit) back into oid[warp][k]
        if (lane < KOUT) {
            int v = (lane > 0 && cnt >= lane + 16) ? oid[warp][lane]
                                                   : oid[warp][0];
            oid[warp][lane] = v;
        }
        __syncwarp();

        // ---- gather epilogue ----
        // xyz: straight from smem (lanes 0..15, k = lane)
        if (lane < KOUT) {
            float4 p = s[oid[warp][lane]];
            size_t ox = (size_t)q * KOUT + lane;
            outx[ox]          = p.x;
            outx[ox + NK]     = p.y;
            outx[ox + 2 * NK] = p.z;
        }

        // feat: 2 passes over channel halves (chunks p*8 + 0..7).
        // Load: 4 LDG.128/pass, instr i covers rows 4i..4i+3 (8 lanes each,
        // 128B contiguous per row). Stage XOR-swizzled: lc ^ (row&7).
        // Store: lane -> (k = lane&15, sub = lane>>4), channel-major STG.32s
        // land as 64B segments.
        int ldrow = lane >> 3;           // 0..3 row-within-group
        int ldlc  = lane & 7;            // chunk within half
        int k     = lane & 15;
        int sub   = lane >> 4;
#pragma unroll
        for (int p = 0; p < 2; p++) {
#pragma unroll
            for (int i = 0; i < 4; i++) {
                int row = 4 * i + ldrow;
                int id = oid[warp][row];
                float4 v = *((const float4*)(fb + (size_t)id * 64)
                             + (p * 8 + ldlc));
                stage[warp][row * 8 + (ldlc ^ (row & 7))] = v;
            }
            __syncwarp();
#pragma unroll
            for (int t = 0; t < 4; t++) {
                int lc = sub * 4 + t;
                float4 v = stage[warp][k * 8 + (lc ^ (k & 7))];
                float* o = outf + (size_t)((p * 8 + lc) * 4) * NK
                                + (size_t)q * KOUT + k;
                o[0]      = v.x;
                o[NK]     = v.y;
                o[2 * NK] = v.z;
                o[3 * NK] = v.w;
            }
            __syncwarp();
        }
    }
}

extern "C" void kernel_launch(void* const* d_in, const int* in_sizes, int n_in,
                              void* d_out, int out_size) {
    const float* xyz  = (const float*)d_in[0];
    const float* feat = (const float*)d_in[1];
    float* out = (float*)d_out;

    cudaFuncSetAttribute(fused_kernel,
                         cudaFuncAttributeMaxDynamicSharedMemorySize,
                         NPTS * sizeof(float4));

    fused_kernel<<<NBLOCKS, TPB, NPTS * sizeof(float4)>>>(xyz, feat, out);
}